// round 8
// baseline (speedup 1.0000x reference)
#include <cuda_runtime.h>
#include <cstdint>

// Problem constants (Pose_Loss: B=65536, D=154)
#define BB   65536
#define DD   154
#define N4   ((BB * DD) / 4)            // 2,523,136 float4s

#define BLOCK_THREADS 256
#define UNROLL 4
#define TILE  (BLOCK_THREADS * UNROLL)  // 1024 float4s per block
#define GRID_BLOCKS (N4 / TILE)         // 2464 blocks, exactly one tile each

static_assert(N4 % TILE == 0, "tile must divide N4");

// Scratch (allocation-free device globals; zero at load, re-zeroed each exec)
__device__ double        g_acc[2];   // [0]=recon, [1]=KLD
__device__ int           g_count;
__device__ unsigned int  g_done;

__device__ __forceinline__ float2 row_weights(int l, int f) {
    // lr in {0,1,2}: use_l <=> l != 1 ; use_r <=> l != 0 ; gated by f != -1
    bool valid = (f != -1);
    return make_float2((valid && l != 1) ? 1.0f : 0.0f,
                       (valid && l != 0) ? 1.0f : 0.0f);
}

__global__ void __launch_bounds__(BLOCK_THREADS, 3)
fused_pose_loss(const float4* __restrict__ rl, const float4* __restrict__ rr,
                const float4* __restrict__ kl, const float4* __restrict__ kr,
                const int* __restrict__ lr,    const int* __restrict__ fpose,
                float* __restrict__ out, int out_size) {
    const unsigned tid = blockIdx.x * blockDim.x + threadIdx.x;

    // ---- Phase A: per-row count (total threads > BB -> at most 1 iter) ----
    int c = 0;
    if (tid < BB) {
        int l = lr[tid];
        if (fpose[tid] != -1)
            c = (l != 1 ? 1 : 0) + (l != 0 ? 1 : 0);
    }

    // ---- Phase B: one tile per block, two load waves of 8 LDG.128 each ----
    const unsigned tbase = blockIdx.x * TILE + threadIdx.x;

    // Per-index row resolution + weights (scalar loads, L1/L2-broadcast)
    unsigned row0[UNROLL], rem[UNROLL];
    float2 w0[UNROLL], w1[UNROLL];
    bool straddle[UNROLL];
    #pragma unroll
    for (int j = 0; j < UNROLL; j++) {
        unsigned i = tbase + j * BLOCK_THREADS;
        unsigned base = i * 4u;
        row0[j] = base / DD;                 // udiv -> mul-hi
        rem[j]  = base - row0[j] * DD;
        w0[j]   = row_weights(lr[row0[j]], fpose[row0[j]]);
        straddle[j] = (rem[j] > (unsigned)(DD - 4));
        if (straddle[j])
            w1[j] = row_weights(lr[row0[j] + 1], fpose[row0[j] + 1]);
    }

    // Wave 1: recon pair
    float rt = 0.0f;
    {
        float4 A[UNROLL], Bv[UNROLL];
        #pragma unroll
        for (int j = 0; j < UNROLL; j++) {
            unsigned i = tbase + j * BLOCK_THREADS;
            A[j]  = rl[i];
            Bv[j] = rr[i];
        }
        #pragma unroll
        for (int j = 0; j < UNROLL; j++) {
            float4 a = A[j], b = Bv[j];
            if (!straddle[j]) {
                rt += w0[j].x * ((a.x + a.y) + (a.z + a.w))
                    + w0[j].y * ((b.x + b.y) + (b.z + b.w));
            } else {
                float ae[4] = {a.x, a.y, a.z, a.w};
                float be[4] = {b.x, b.y, b.z, b.w};
                #pragma unroll
                for (int e = 0; e < 4; e++) {
                    float2 w = ((rem[j] + e) >= (unsigned)DD) ? w1[j] : w0[j];
                    rt += w.x * ae[e] + w.y * be[e];
                }
            }
        }
    }

    // Wave 2: KLD pair
    float kt = 0.0f;
    {
        float4 Cv[UNROLL], Dv[UNROLL];
        #pragma unroll
        for (int j = 0; j < UNROLL; j++) {
            unsigned i = tbase + j * BLOCK_THREADS;
            Cv[j] = kl[i];
            Dv[j] = kr[i];
        }
        #pragma unroll
        for (int j = 0; j < UNROLL; j++) {
            float4 cc = Cv[j], d = Dv[j];
            if (!straddle[j]) {
                kt += w0[j].x * ((cc.x + cc.y) + (cc.z + cc.w))
                    + w0[j].y * ((d.x + d.y) + (d.z + d.w));
            } else {
                float ce[4] = {cc.x, cc.y, cc.z, cc.w};
                float de[4] = {d.x, d.y, d.z, d.w};
                #pragma unroll
                for (int e = 0; e < 4; e++) {
                    float2 w = ((rem[j] + e) >= (unsigned)DD) ? w1[j] : w0[j];
                    kt += w.x * ce[e] + w.y * de[e];
                }
            }
        }
    }

    double racc = (double)rt;
    double kacc = (double)kt;

    // ---- Phase C: block reduction ----
    #pragma unroll
    for (int off = 16; off > 0; off >>= 1) {
        racc += __shfl_down_sync(0xFFFFFFFFu, racc, off);
        kacc += __shfl_down_sync(0xFFFFFFFFu, kacc, off);
        c    += __shfl_down_sync(0xFFFFFFFFu, c,    off);
    }

    __shared__ double s_r[8], s_k[8];
    __shared__ int    s_c[8];
    int wid = threadIdx.x >> 5;
    int lid = threadIdx.x & 31;
    if (lid == 0) { s_r[wid] = racc; s_k[wid] = kacc; s_c[wid] = c; }
    __syncthreads();

    if (wid == 0) {
        int nw = blockDim.x >> 5;
        double br = (lid < nw) ? s_r[lid] : 0.0;
        double bk = (lid < nw) ? s_k[lid] : 0.0;
        int    bc = (lid < nw) ? s_c[lid] : 0;
        #pragma unroll
        for (int off = 4; off > 0; off >>= 1) {
            br += __shfl_down_sync(0xFFFFFFFFu, br, off);
            bk += __shfl_down_sync(0xFFFFFFFFu, bk, off);
            bc += __shfl_down_sync(0xFFFFFFFFu, bc, off);
        }
        if (lid == 0) {
            atomicAdd(&g_acc[0], br);
            atomicAdd(&g_acc[1], bk);
            if (bc) atomicAdd(&g_count, bc);
        }
    }

    // ---- Phase D: last-block finalize + reset ----
    __shared__ bool is_last;
    if (threadIdx.x == 0) {
        __threadfence();
        unsigned t = atomicAdd(&g_done, 1u);
        is_last = (t == gridDim.x - 1);
    }
    __syncthreads();
    if (is_last && threadIdx.x == 0) {
        __threadfence();
        double vr = g_acc[0];
        double vk = g_acc[1];
        int    vc = g_count;
        if (out_size > 0) out[0] = (float)(vr / 154.0);
        if (out_size > 1) out[1] = (float)vk;
        if (out_size > 2) out[2] = (float)vc;
        g_acc[0] = 0.0;
        g_acc[1] = 0.0;
        g_count  = 0;
        __threadfence();
        g_done   = 0;
    }
}

extern "C" void kernel_launch(void* const* d_in, const int* in_sizes, int n_in,
                              void* d_out, int out_size) {
    const float4* rl = (const float4*)d_in[0];
    const float4* rr = (const float4*)d_in[1];
    const float4* kl = (const float4*)d_in[2];
    const float4* kr = (const float4*)d_in[3];
    const int* lr    = (const int*)d_in[4];
    const int* fpose = (const int*)d_in[5];
    float* out = (float*)d_out;

    fused_pose_loss<<<GRID_BLOCKS, BLOCK_THREADS>>>(rl, rr, kl, kr, lr, fpose,
                                                    out, out_size);
}

// round 9
// speedup vs baseline: 1.1583x; 1.1583x over previous
#include <cuda_runtime.h>
#include <cstdint>

// Problem constants (Pose_Loss: B=65536, D=154)
#define BB   65536
#define DD   154
#define N4   ((BB * DD) / 4)        // 2,523,136 float4s per array

#define BLOCK_THREADS 256
#define T4   256                    // float4s per array per tile (1 per thread)
#define NTILES (N4 / T4)            // 9856 tiles
static_assert(N4 % T4 == 0, "tile must divide N4");

#define TILE_BYTES (T4 * 16)        // 4096 B per array per tile
#define STAGE_BYTES (4 * TILE_BYTES)// 16384 B per stage (all 4 arrays)

#define BLOCKS_PER_SM 6
#define GRID_BLOCKS (152 * BLOCKS_PER_SM)   // 912

// Scratch (allocation-free device globals; zero at load, re-zeroed each exec)
__device__ double        g_acc[2];   // [0]=recon, [1]=KLD
__device__ int           g_count;
__device__ unsigned int  g_done;

__device__ __forceinline__ unsigned smem_u32(const void* p) {
    unsigned a;
    asm("{ .reg .u64 t; cvta.to.shared.u64 t, %1; cvt.u32.u64 %0, t; }"
        : "=r"(a) : "l"(p));
    return a;
}

__device__ __forceinline__ void mbar_init(unsigned mbar, unsigned count) {
    asm volatile("mbarrier.init.shared.b64 [%0], %1;"
                 :: "r"(mbar), "r"(count) : "memory");
}

__device__ __forceinline__ void mbar_expect_tx(unsigned mbar, unsigned bytes) {
    asm volatile("mbarrier.arrive.expect_tx.shared.b64 _, [%0], %1;"
                 :: "r"(mbar), "r"(bytes) : "memory");
}

__device__ __forceinline__ void bulk_ldg(unsigned dst_smem, const void* src,
                                         unsigned bytes, unsigned mbar) {
    asm volatile(
        "cp.async.bulk.shared::cluster.global.mbarrier::complete_tx::bytes "
        "[%0], [%1], %2, [%3];"
        :: "r"(dst_smem), "l"(src), "r"(bytes), "r"(mbar) : "memory");
}

__device__ __forceinline__ void mbar_wait(unsigned mbar, unsigned parity) {
    asm volatile(
        "{\n\t"
        ".reg .pred P;\n\t"
        "W%=:\n\t"
        "mbarrier.try_wait.parity.acquire.cta.shared::cta.b64 P, [%0], %1, 0x989680;\n\t"
        "@P bra D%=;\n\t"
        "bra W%=;\n\t"
        "D%=:\n\t"
        "}"
        :: "r"(mbar), "r"(parity) : "memory");
}

__device__ __forceinline__ float2 row_weights(int l, int f) {
    // lr in {0,1,2}: use_l <=> l != 1 ; use_r <=> l != 0 ; gated by f != -1
    bool valid = (f != -1);
    return make_float2((valid && l != 1) ? 1.0f : 0.0f,
                       (valid && l != 0) ? 1.0f : 0.0f);
}

__global__ void __launch_bounds__(BLOCK_THREADS)
fused_pose_loss(const char* __restrict__ rl, const char* __restrict__ rr,
                const char* __restrict__ kl, const char* __restrict__ kr,
                const int* __restrict__ lr,  const int* __restrict__ fpose,
                float* __restrict__ out, int out_size) {
    // 2 stages x 4 arrays x 256 float4 = 32 KB static smem
    __shared__ __align__(16) float4 sbuf[2][4][T4];
    __shared__ __align__(8)  unsigned long long mbar_storage[2];

    const int tid  = threadIdx.x;
    const unsigned gtid = blockIdx.x * BLOCK_THREADS + tid;
    const unsigned mb0 = smem_u32(&mbar_storage[0]);
    const unsigned mb1 = smem_u32(&mbar_storage[1]);

    // ---- Phase A: per-row count (grid 912*256 = 233K threads > BB) ----
    int c = 0;
    if (gtid < BB) {
        int l = lr[gtid];
        if (fpose[gtid] != -1)
            c = (l != 1 ? 1 : 0) + (l != 0 ? 1 : 0);
    }

    if (tid == 0) {
        mbar_init(mb0, 1);
        mbar_init(mb1, 1);
    }
    __syncthreads();

    // ---- Phase B: double-buffered bulk-async streaming reduction ----
    const unsigned stride = gridDim.x;   // tiles advance by grid size
    unsigned tile0 = blockIdx.x;

    // prefetch first tile into buffer 0
    if (tid == 0) {
        size_t off = (size_t)tile0 * TILE_BYTES;
        mbar_expect_tx(mb0, STAGE_BYTES);
        bulk_ldg(smem_u32(&sbuf[0][0][0]), rl + off, TILE_BYTES, mb0);
        bulk_ldg(smem_u32(&sbuf[0][1][0]), rr + off, TILE_BYTES, mb0);
        bulk_ldg(smem_u32(&sbuf[0][2][0]), kl + off, TILE_BYTES, mb0);
        bulk_ldg(smem_u32(&sbuf[0][3][0]), kr + off, TILE_BYTES, mb0);
    }

    double racc = 0.0, kacc = 0.0;
    int buf = 0;
    int ph0 = 0, ph1 = 0;

    for (unsigned t = tile0; t < NTILES; t += stride) {
        // prefetch next tile into the other buffer (free since the
        // __syncthreads at the end of the previous iteration)
        unsigned nxt = t + stride;
        if (tid == 0 && nxt < NTILES) {
            unsigned mbn = buf ? mb0 : mb1;
            int bn = buf ^ 1;
            size_t off = (size_t)nxt * TILE_BYTES;
            mbar_expect_tx(mbn, STAGE_BYTES);
            bulk_ldg(smem_u32(&sbuf[bn][0][0]), rl + off, TILE_BYTES, mbn);
            bulk_ldg(smem_u32(&sbuf[bn][1][0]), rr + off, TILE_BYTES, mbn);
            bulk_ldg(smem_u32(&sbuf[bn][2][0]), kl + off, TILE_BYTES, mbn);
            bulk_ldg(smem_u32(&sbuf[bn][3][0]), kr + off, TILE_BYTES, mbn);
        }

        // row resolution + weights for this thread's element (L2-resident)
        unsigned i    = t * T4 + tid;            // global float4 index
        unsigned base = i * 4u;
        unsigned row0 = base / DD;               // udiv -> mul-hi
        unsigned rem  = base - row0 * DD;
        float2 w0 = row_weights(lr[row0], fpose[row0]);
        bool straddle = (rem > (unsigned)(DD - 4));
        float2 w1 = w0;
        if (straddle)
            w1 = row_weights(lr[row0 + 1], fpose[row0 + 1]);

        // wait for this buffer's data
        if (buf) { mbar_wait(mb1, ph1); ph1 ^= 1; }
        else     { mbar_wait(mb0, ph0); ph0 ^= 1; }

        float4 a  = sbuf[buf][0][tid];
        float4 b  = sbuf[buf][1][tid];
        float4 cc = sbuf[buf][2][tid];
        float4 d  = sbuf[buf][3][tid];

        float rt, kt;
        if (!straddle) {
            rt = w0.x * ((a.x + a.y) + (a.z + a.w))
               + w0.y * ((b.x + b.y) + (b.z + b.w));
            kt = w0.x * ((cc.x + cc.y) + (cc.z + cc.w))
               + w0.y * ((d.x + d.y) + (d.z + d.w));
        } else {
            float ae[4] = {a.x, a.y, a.z, a.w};
            float be[4] = {b.x, b.y, b.z, b.w};
            float ce[4] = {cc.x, cc.y, cc.z, cc.w};
            float de[4] = {d.x, d.y, d.z, d.w};
            rt = 0.0f; kt = 0.0f;
            #pragma unroll
            for (int e = 0; e < 4; e++) {
                float2 w = ((rem + e) >= (unsigned)DD) ? w1 : w0;
                rt += w.x * ae[e] + w.y * be[e];
                kt += w.x * ce[e] + w.y * de[e];
            }
        }
        racc += (double)rt;
        kacc += (double)kt;

        __syncthreads();   // everyone done reading sbuf[buf] before reuse
        buf ^= 1;
    }

    // ---- Phase C: block reduction ----
    #pragma unroll
    for (int off = 16; off > 0; off >>= 1) {
        racc += __shfl_down_sync(0xFFFFFFFFu, racc, off);
        kacc += __shfl_down_sync(0xFFFFFFFFu, kacc, off);
        c    += __shfl_down_sync(0xFFFFFFFFu, c,    off);
    }

    __shared__ double s_r[8], s_k[8];
    __shared__ int    s_c[8];
    int wid = threadIdx.x >> 5;
    int lid = threadIdx.x & 31;
    if (lid == 0) { s_r[wid] = racc; s_k[wid] = kacc; s_c[wid] = c; }
    __syncthreads();

    if (wid == 0) {
        int nw = blockDim.x >> 5;
        double br = (lid < nw) ? s_r[lid] : 0.0;
        double bk = (lid < nw) ? s_k[lid] : 0.0;
        int    bc = (lid < nw) ? s_c[lid] : 0;
        #pragma unroll
        for (int off = 4; off > 0; off >>= 1) {
            br += __shfl_down_sync(0xFFFFFFFFu, br, off);
            bk += __shfl_down_sync(0xFFFFFFFFu, bk, off);
            bc += __shfl_down_sync(0xFFFFFFFFu, bc, off);
        }
        if (lid == 0) {
            atomicAdd(&g_acc[0], br);
            atomicAdd(&g_acc[1], bk);
            if (bc) atomicAdd(&g_count, bc);
        }
    }

    // ---- Phase D: last-block finalize + reset ----
    __shared__ bool is_last;
    if (threadIdx.x == 0) {
        __threadfence();
        unsigned tkt = atomicAdd(&g_done, 1u);
        is_last = (tkt == gridDim.x - 1);
    }
    __syncthreads();
    if (is_last && threadIdx.x == 0) {
        __threadfence();
        double vr = g_acc[0];
        double vk = g_acc[1];
        int    vc = g_count;
        if (out_size > 0) out[0] = (float)(vr / 154.0);
        if (out_size > 1) out[1] = (float)vk;
        if (out_size > 2) out[2] = (float)vc;
        g_acc[0] = 0.0;
        g_acc[1] = 0.0;
        g_count  = 0;
        __threadfence();
        g_done   = 0;
    }
}

extern "C" void kernel_launch(void* const* d_in, const int* in_sizes, int n_in,
                              void* d_out, int out_size) {
    const char* rl = (const char*)d_in[0];
    const char* rr = (const char*)d_in[1];
    const char* kl = (const char*)d_in[2];
    const char* kr = (const char*)d_in[3];
    const int* lr    = (const int*)d_in[4];
    const int* fpose = (const int*)d_in[5];
    float* out = (float*)d_out;

    fused_pose_loss<<<GRID_BLOCKS, BLOCK_THREADS>>>(rl, rr, kl, kr, lr, fpose,
                                                    out, out_size);
}

// round 10
// speedup vs baseline: 1.1712x; 1.0111x over previous
#include <cuda_runtime.h>
#include <cstdint>

// Problem constants (Pose_Loss: B=65536, D=154)
#define BB   65536
#define DD   154
#define N4   ((BB * DD) / 4)        // 2,523,136 float4s per array

#define BLOCK_THREADS 256
#define T4   256                    // float4s per array per stage (1/thread)
#define NTILES (N4 / T4)            // 9856 tiles
static_assert(N4 % T4 == 0, "tile must divide N4");

#define TILE_BYTES  (T4 * 16)           // 4096 B per array
#define STAGE_BYTES (4 * TILE_BYTES)    // 16384 B per stage (all 4 arrays)
#define STAGES 4
#define LOOKAHEAD (STAGES - 1)          // 3 outstanding transfers

#define GRID_BLOCKS 448                 // 9856 / 448 = exactly 22 tiles/block
static_assert(NTILES % GRID_BLOCKS == 0, "perfect balance");

// dynamic smem: 4 stages + 4 mbarriers
#define MBAR_OFF (STAGES * STAGE_BYTES)
#define DYN_SMEM (MBAR_OFF + STAGES * 8)

// Scratch (allocation-free device globals; zero at load, re-zeroed each exec)
__device__ double        g_acc[2];   // [0]=recon, [1]=KLD
__device__ int           g_count;
__device__ unsigned int  g_done;

__device__ __forceinline__ unsigned smem_u32(const void* p) {
    unsigned a;
    asm("{ .reg .u64 t; cvta.to.shared.u64 t, %1; cvt.u32.u64 %0, t; }"
        : "=r"(a) : "l"(p));
    return a;
}

__device__ __forceinline__ void mbar_init(unsigned mbar, unsigned count) {
    asm volatile("mbarrier.init.shared.b64 [%0], %1;"
                 :: "r"(mbar), "r"(count) : "memory");
}

__device__ __forceinline__ void mbar_expect_tx(unsigned mbar, unsigned bytes) {
    asm volatile("mbarrier.arrive.expect_tx.shared.b64 _, [%0], %1;"
                 :: "r"(mbar), "r"(bytes) : "memory");
}

__device__ __forceinline__ void bulk_ldg(unsigned dst_smem, const void* src,
                                         unsigned bytes, unsigned mbar) {
    asm volatile(
        "cp.async.bulk.shared::cluster.global.mbarrier::complete_tx::bytes "
        "[%0], [%1], %2, [%3];"
        :: "r"(dst_smem), "l"(src), "r"(bytes), "r"(mbar) : "memory");
}

__device__ __forceinline__ void mbar_wait(unsigned mbar, unsigned parity) {
    asm volatile(
        "{\n\t"
        ".reg .pred P;\n\t"
        "W%=:\n\t"
        "mbarrier.try_wait.parity.acquire.cta.shared::cta.b64 P, [%0], %1, 0x989680;\n\t"
        "@P bra D%=;\n\t"
        "bra W%=;\n\t"
        "D%=:\n\t"
        "}"
        :: "r"(mbar), "r"(parity) : "memory");
}

__device__ __forceinline__ float2 row_weights(int l, int f) {
    // lr in {0,1,2}: use_l <=> l != 1 ; use_r <=> l != 0 ; gated by f != -1
    bool valid = (f != -1);
    return make_float2((valid && l != 1) ? 1.0f : 0.0f,
                       (valid && l != 0) ? 1.0f : 0.0f);
}

__global__ void __launch_bounds__(BLOCK_THREADS)
fused_pose_loss(const char* __restrict__ rl, const char* __restrict__ rr,
                const char* __restrict__ kl, const char* __restrict__ kr,
                const int* __restrict__ lr,  const int* __restrict__ fpose,
                float* __restrict__ out, int out_size) {
    extern __shared__ __align__(16) char dynsmem[];
    const unsigned sbase = smem_u32(dynsmem);

    const int tid  = threadIdx.x;
    const unsigned gtid = blockIdx.x * BLOCK_THREADS + tid;

    // ---- Phase A: per-row count (448*256 = 114,688 threads > BB) ----
    int c = 0;
    if (gtid < BB) {
        int l = lr[gtid];
        if (fpose[gtid] != -1)
            c = (l != 1 ? 1 : 0) + (l != 0 ? 1 : 0);
    }

    if (tid == 0) {
        #pragma unroll
        for (int s = 0; s < STAGES; s++)
            mbar_init(sbase + MBAR_OFF + s * 8, 1);
    }
    __syncthreads();

    // ---- Phase B: 4-stage ring, 3 outstanding bulk transfers per block ----
    const unsigned stride = gridDim.x;            // 448
    const unsigned t0 = blockIdx.x;

    // helper to issue one stage's 4 bulk copies
    auto issue = [&](unsigned tile, int stage) {
        unsigned mb = sbase + MBAR_OFF + stage * 8;
        unsigned dst = sbase + stage * STAGE_BYTES;
        size_t off = (size_t)tile * TILE_BYTES;
        mbar_expect_tx(mb, STAGE_BYTES);
        bulk_ldg(dst,                  rl + off, TILE_BYTES, mb);
        bulk_ldg(dst + TILE_BYTES,     rr + off, TILE_BYTES, mb);
        bulk_ldg(dst + 2 * TILE_BYTES, kl + off, TILE_BYTES, mb);
        bulk_ldg(dst + 3 * TILE_BYTES, kr + off, TILE_BYTES, mb);
    };

    // prime the pipeline: stages 0..2
    if (tid == 0) {
        #pragma unroll
        for (int s = 0; s < LOOKAHEAD; s++) {
            unsigned tile = t0 + s * stride;
            if (tile < NTILES) issue(tile, s);
        }
    }

    double racc = 0.0, kacc = 0.0;
    int k = 0;

    for (unsigned t = t0; t < NTILES; t += stride, k++) {
        // refill: issue tile t+3*stride into stage (k+3)&3. That buffer was
        // consumed at iteration k-1; its reuse is protected by the
        // __syncthreads at the end of iteration k-1.
        unsigned nt = t + LOOKAHEAD * stride;
        if (tid == 0 && nt < NTILES)
            issue(nt, (k + LOOKAHEAD) & (STAGES - 1));

        // row resolution + weights (L2-resident scalar loads; issued before
        // the wait so their latency hides under the transfer wait)
        unsigned i    = t * T4 + tid;
        unsigned base = i * 4u;
        unsigned row0 = base / DD;               // udiv -> mul-hi
        unsigned rem  = base - row0 * DD;
        float2 w0 = row_weights(lr[row0], fpose[row0]);
        bool straddle = (rem > (unsigned)(DD - 4));
        float2 w1 = w0;
        if (straddle)
            w1 = row_weights(lr[row0 + 1], fpose[row0 + 1]);

        // wait for this stage's data
        int stage = k & (STAGES - 1);
        mbar_wait(sbase + MBAR_OFF + stage * 8, (k >> 2) & 1);

        const float4* sb = (const float4*)(dynsmem + stage * STAGE_BYTES);
        float4 a  = sb[tid];
        float4 b  = sb[T4 + tid];
        float4 cc = sb[2 * T4 + tid];
        float4 d  = sb[3 * T4 + tid];

        float rt, kt;
        if (!straddle) {
            rt = w0.x * ((a.x + a.y) + (a.z + a.w))
               + w0.y * ((b.x + b.y) + (b.z + b.w));
            kt = w0.x * ((cc.x + cc.y) + (cc.z + cc.w))
               + w0.y * ((d.x + d.y) + (d.z + d.w));
        } else {
            float ae[4] = {a.x, a.y, a.z, a.w};
            float be[4] = {b.x, b.y, b.z, b.w};
            float ce[4] = {cc.x, cc.y, cc.z, cc.w};
            float de[4] = {d.x, d.y, d.z, d.w};
            rt = 0.0f; kt = 0.0f;
            #pragma unroll
            for (int e = 0; e < 4; e++) {
                float2 w = ((rem + e) >= (unsigned)DD) ? w1 : w0;
                rt += w.x * ae[e] + w.y * be[e];
                kt += w.x * ce[e] + w.y * de[e];
            }
        }
        racc += (double)rt;
        kacc += (double)kt;

        __syncthreads();   // all threads done reading this stage
    }

    // ---- Phase C: block reduction ----
    #pragma unroll
    for (int off = 16; off > 0; off >>= 1) {
        racc += __shfl_down_sync(0xFFFFFFFFu, racc, off);
        kacc += __shfl_down_sync(0xFFFFFFFFu, kacc, off);
        c    += __shfl_down_sync(0xFFFFFFFFu, c,    off);
    }

    __shared__ double s_r[8], s_k[8];
    __shared__ int    s_c[8];
    int wid = threadIdx.x >> 5;
    int lid = threadIdx.x & 31;
    if (lid == 0) { s_r[wid] = racc; s_k[wid] = kacc; s_c[wid] = c; }
    __syncthreads();

    if (wid == 0) {
        int nw = blockDim.x >> 5;
        double br = (lid < nw) ? s_r[lid] : 0.0;
        double bk = (lid < nw) ? s_k[lid] : 0.0;
        int    bc = (lid < nw) ? s_c[lid] : 0;
        #pragma unroll
        for (int off = 4; off > 0; off >>= 1) {
            br += __shfl_down_sync(0xFFFFFFFFu, br, off);
            bk += __shfl_down_sync(0xFFFFFFFFu, bk, off);
            bc += __shfl_down_sync(0xFFFFFFFFu, bc, off);
        }
        if (lid == 0) {
            atomicAdd(&g_acc[0], br);
            atomicAdd(&g_acc[1], bk);
            if (bc) atomicAdd(&g_count, bc);
        }
    }

    // ---- Phase D: last-block finalize + reset ----
    __shared__ bool is_last;
    if (threadIdx.x == 0) {
        __threadfence();
        unsigned tkt = atomicAdd(&g_done, 1u);
        is_last = (tkt == gridDim.x - 1);
    }
    __syncthreads();
    if (is_last && threadIdx.x == 0) {
        __threadfence();
        double vr = g_acc[0];
        double vk = g_acc[1];
        int    vc = g_count;
        if (out_size > 0) out[0] = (float)(vr / 154.0);
        if (out_size > 1) out[1] = (float)vk;
        if (out_size > 2) out[2] = (float)vc;
        g_acc[0] = 0.0;
        g_acc[1] = 0.0;
        g_count  = 0;
        __threadfence();
        g_done   = 0;
    }
}

extern "C" void kernel_launch(void* const* d_in, const int* in_sizes, int n_in,
                              void* d_out, int out_size) {
    const char* rl = (const char*)d_in[0];
    const char* rr = (const char*)d_in[1];
    const char* kl = (const char*)d_in[2];
    const char* kr = (const char*)d_in[3];
    const int* lr    = (const int*)d_in[4];
    const int* fpose = (const int*)d_in[5];
    float* out = (float*)d_out;

    // raise dynamic smem cap (immediate host call; not a graph node, no alloc)
    cudaFuncSetAttribute(fused_pose_loss,
                         cudaFuncAttributeMaxDynamicSharedMemorySize, DYN_SMEM);

    fused_pose_loss<<<GRID_BLOCKS, BLOCK_THREADS, DYN_SMEM>>>(
        rl, rr, kl, kr, lr, fpose, out, out_size);
}